// round 4
// baseline (speedup 1.0000x reference)
#include <cuda_runtime.h>
#include <math.h>

// Problem shape (fixed by the dataset)
#define BB 4
#define NN 2048
#define CC 3
#define MM 4096          // NN * (CC-1) candidates per image
#define NW 64            // MM/64 mask words per row
#define MAXDET 100

#define SCORE_THR 0.05f
#define NMS_THR   0.5f
#define MIN_SIZE  0.01f

// ---------------- device scratch (static; no allocation APIs) ----------------
__device__ unsigned long long g_keys[BB][MM];
__device__ float4 g_boxes[BB][MM];
__device__ float  g_sc[BB][MM];
__device__ float4 g_sb[BB][MM];    // sorted boxes (plain)
__device__ float4 g_sob[BB][MM];   // sorted boxes + class offset (for IoU)
__device__ float  g_ss[BB][MM];    // sorted scores
__device__ int    g_slab[BB][MM];  // sorted labels
__device__ int    g_V[BB];         // valid count per image
__device__ unsigned long long g_mask[BB][MM][NW];  // 8 MB suppression matrix (zero-init; lower-tri never written)

// Correctly-rounded f32 exp via double (and immune to fast-math)
__device__ __forceinline__ float exact_expf(float x) { return (float)exp((double)x); }

__device__ __forceinline__ float read_dim(const void* p) {
    if (p == nullptr) return 800.0f;
    int vi = *(const int*)p;
    if (vi > 0 && vi < 1000000) return (float)vi;
    float vf = *(const float*)p;
    return (vf > 0.0f && vf < 1.0e6f) ? vf : 800.0f;
}

// ---------------- K1: softmax + decode + clip + key build ----------------
__global__ void k1_decode(const float* __restrict__ logits,
                          const float* __restrict__ reg,
                          const float* __restrict__ props,
                          const void* hp, const void* wp)
{
    const float SCLAMP = 4.135166556742356f;  // log(1000/16) rounded to f32
    int t = blockIdx.x * blockDim.x + threadIdx.x;
    if (t >= BB * NN) return;
    int img = t >> 11;
    int n   = t & (NN - 1);

    float Hf = read_dim(hp);
    float Wf = read_dim(wp);

    // softmax over 3 logits (sub max, exp, / sum) — mirrors jax.nn.softmax
    const float* lg = logits + (size_t)(img * NN + n) * CC;
    float l0 = lg[0], l1 = lg[1], l2 = lg[2];
    float mxl = fmaxf(l0, fmaxf(l1, l2));
    float e0 = exact_expf(__fsub_rn(l0, mxl));
    float e1 = exact_expf(__fsub_rn(l1, mxl));
    float e2 = exact_expf(__fsub_rn(l2, mxl));
    float s  = __fadd_rn(__fadd_rn(e0, e1), e2);
    float scr[2];
    scr[0] = __fdiv_rn(e1, s);
    scr[1] = __fdiv_rn(e2, s);

    const float* pr = props + (size_t)(img * NN + n) * 4;
    float x1 = pr[0], y1 = pr[1], x2 = pr[2], y2 = pr[3];
    float w  = __fsub_rn(x2, x1);
    float h  = __fsub_rn(y2, y1);
    float cx = __fadd_rn(x1, __fmul_rn(0.5f, w));
    float cy = __fadd_rn(y1, __fmul_rn(0.5f, h));

    const float* rg = reg + (size_t)(img * NN + n) * (4 * CC);

    #pragma unroll
    for (int c = 1; c <= 2; ++c) {
        const float* r = rg + 4 * c;
        float dx = __fdiv_rn(r[0], 10.0f);
        float dy = __fdiv_rn(r[1], 10.0f);
        float dw = fminf(__fdiv_rn(r[2], 5.0f), SCLAMP);
        float dh = fminf(__fdiv_rn(r[3], 5.0f), SCLAMP);
        float pcx = __fadd_rn(__fmul_rn(dx, w), cx);
        float pcy = __fadd_rn(__fmul_rn(dy, h), cy);
        float pw  = __fmul_rn(exact_expf(dw), w);
        float ph  = __fmul_rn(exact_expf(dh), h);
        float bx1 = __fsub_rn(pcx, __fmul_rn(0.5f, pw));
        float by1 = __fsub_rn(pcy, __fmul_rn(0.5f, ph));
        float bx2 = __fadd_rn(pcx, __fmul_rn(0.5f, pw));
        float by2 = __fadd_rn(pcy, __fmul_rn(0.5f, ph));
        bx1 = fminf(fmaxf(bx1, 0.0f), Wf);
        by1 = fminf(fmaxf(by1, 0.0f), Hf);
        bx2 = fminf(fmaxf(bx2, 0.0f), Wf);
        by2 = fminf(fmaxf(by2, 0.0f), Hf);

        int m = n * 2 + (c - 1);
        g_boxes[img][m] = make_float4(bx1, by1, bx2, by2);
        float sc = scr[c - 1];
        g_sc[img][m] = sc;

        bool valid = (sc > SCORE_THR)
                  && (__fsub_rn(bx2, bx1) >= MIN_SIZE)
                  && (__fsub_rn(by2, by1) >= MIN_SIZE);
        unsigned scu = valid ? __float_as_uint(sc) : 0u;  // positive floats: bits monotonic
        g_keys[img][m] = (((unsigned long long)(0x7FFFFFFFu - scu)) << 12) | (unsigned)m;
    }
}

// ---------------- K2: per-image bitonic sort + gmax + gather ----------------
__global__ void k2_sort()
{
    __shared__ unsigned long long sk[MM];   // 32 KB
    __shared__ float sred[512];
    __shared__ int scnt;

    int img = blockIdx.x;
    int tid = threadIdx.x;

    for (int i = tid; i < MM; i += 512) sk[i] = g_keys[img][i];

    // max box coordinate (all >= 0 after clip)
    float mx = 0.0f;
    for (int i = tid; i < MM; i += 512) {
        float4 b = g_boxes[img][i];
        mx = fmaxf(mx, fmaxf(fmaxf(b.x, b.y), fmaxf(b.z, b.w)));
    }
    sred[tid] = mx;
    __syncthreads();
    #pragma unroll
    for (int s = 256; s > 0; s >>= 1) {
        if (tid < s) sred[tid] = fmaxf(sred[tid], sred[tid + s]);
        __syncthreads();
    }
    float base_off = __fadd_rn(sred[0], 1.0f);

    // bitonic sort, ascending (key = descending score, stable by index)
    for (int k = 2; k <= MM; k <<= 1) {
        for (int j = k >> 1; j > 0; j >>= 1) {
            __syncthreads();
            for (int i = tid; i < MM; i += 512) {
                int l = i ^ j;
                if (l > i) {
                    unsigned long long a = sk[i], b = sk[l];
                    bool up = ((i & k) == 0);
                    if ((a > b) == up) { sk[i] = b; sk[l] = a; }
                }
            }
        }
    }
    __syncthreads();

    if (tid == 0) scnt = 0;
    __syncthreads();

    int local = 0;
    for (int i = tid; i < MM; i += 512) {
        unsigned long long key = sk[i];
        int m = (int)(key & 0xFFFull);
        if ((key >> 12) != 0x7FFFFFFFull) local++;
        float4 b = g_boxes[img][m];
        int lab = (m & 1) + 1;
        float off = __fmul_rn((float)lab, base_off);
        g_sb[img][i]  = b;
        g_sob[img][i] = make_float4(__fadd_rn(b.x, off), __fadd_rn(b.y, off),
                                    __fadd_rn(b.z, off), __fadd_rn(b.w, off));
        g_ss[img][i]   = g_sc[img][m];
        g_slab[img][i] = lab;
    }
    atomicAdd(&scnt, local);
    __syncthreads();
    if (tid == 0) g_V[img] = scnt;
}

// ---------------- K3: suppression bit-matrix (upper triangle only) ----------------
__global__ void k3_mask()
{
    int img = blockIdx.z, rc = blockIdx.y, cc = blockIdx.x;
    if (cc < rc) return;                       // strictly-lower words never read (stay 0)
    int V = g_V[img];
    V = max(0, min(V, MM));
    if (rc * 64 >= V || cc * 64 >= V) return;  // beyond valid prefix never read (stay 0)

    __shared__ float4 cb[64];
    __shared__ float  ca[64];
    int t = threadIdx.x;

    float4 q = g_sob[img][cc * 64 + t];
    cb[t] = q;
    ca[t] = __fmul_rn(__fsub_rn(q.z, q.x), __fsub_rn(q.w, q.y));
    __syncthreads();

    int i = rc * 64 + t;
    float4 a = g_sob[img][i];
    float aa = __fmul_rn(__fsub_rn(a.z, a.x), __fsub_rn(a.w, a.y));

    unsigned long long bits = 0ull;
    int jstart = (cc == rc) ? (t + 1) : 0;
    for (int jj = jstart; jj < 64; ++jj) {
        float4 b = cb[jj];
        float lx = fmaxf(a.x, b.x), ly = fmaxf(a.y, b.y);
        float rx = fminf(a.z, b.z), ry = fminf(a.w, b.w);
        float wd = fmaxf(__fsub_rn(rx, lx), 0.0f);
        float hg = fmaxf(__fsub_rn(ry, ly), 0.0f);
        float inter = __fmul_rn(wd, hg);
        if (inter > 0.0f) {  // iou==0 can't exceed thr; skips the precise FDIV
            float den = __fadd_rn(__fsub_rn(__fadd_rn(aa, ca[jj]), inter), 1e-7f);
            if (__fdiv_rn(inter, den) > NMS_THR) bits |= (1ull << jj);
        }
    }
    g_mask[img][i][cc] = bits;
}

// ---------------- K4: single-warp greedy scan (NO __syncthreads) + output ----------------
__global__ void k4_scan(float* __restrict__ out)
{
    int img  = blockIdx.x;
    int lane = threadIdx.x;           // blockDim = 32
    int V = g_V[img];
    V = max(0, min(V, MM));

    __shared__ int kept[MAXDET];

    // remv bitset distributed over the warp: lane owns words {lane, lane+32}
    unsigned long long r0 = 0ull, r1 = 0ull;
    int cnt = 0;

    // software-pipelined row prefetch: loads for row i+1 issue during row i
    unsigned long long m0 = 0ull, m1 = 0ull;
    if (V > 0) { m0 = g_mask[img][0][lane]; m1 = g_mask[img][0][lane + 32]; }

    for (int i = 0; i < V && cnt < MAXDET; ++i) {
        unsigned long long n0 = 0ull, n1 = 0ull;
        if (i + 1 < V) { n0 = g_mask[img][i + 1][lane]; n1 = g_mask[img][i + 1][lane + 32]; }

        int w = i >> 6, b = i & 63;
        unsigned long long src = (w & 32) ? r1 : r0;          // w uniform across warp
        unsigned long long rv  = __shfl_sync(0xFFFFFFFFu, src, w & 31);
        if (!((rv >> b) & 1ull)) {                            // uniform branch
            if (lane == 0) kept[cnt] = i;
            cnt++;
            r0 |= m0; r1 |= m1;                               // unwritten words are 0: harmless
        }
        m0 = n0; m1 = n1;
    }
    __syncwarp();

    // output layout (assumed flatten-concat, all f32):
    // boxes [B,100,4] | scores [B,100] | labels [B,100] | keep [B,100]
    float* oB = out;
    float* oS = out + BB * MAXDET * 4;
    float* oL = oS + BB * MAXDET;
    float* oK = oL + BB * MAXDET;

    for (int r = lane; r < MAXDET; r += 32) {
        float4 bx = make_float4(0.f, 0.f, 0.f, 0.f);
        float sc = 0.f, lbf = 0.f, kp = 0.f;
        if (r < cnt) {
            int id = kept[r];
            bx  = g_sb[img][id];
            sc  = g_ss[img][id];
            lbf = (float)g_slab[img][id];
            kp  = 1.0f;
        }
        float* bptr = oB + (size_t)(img * MAXDET + r) * 4;
        bptr[0] = bx.x; bptr[1] = bx.y; bptr[2] = bx.z; bptr[3] = bx.w;
        oS[img * MAXDET + r] = sc;
        oL[img * MAXDET + r] = lbf;
        oK[img * MAXDET + r] = kp;
    }
}

// ---------------- launch ----------------
extern "C" void kernel_launch(void* const* d_in, const int* in_sizes, int n_in,
                              void* d_out, int out_size)
{
    const float* logits = (const float*)d_in[0];
    const float* reg    = (const float*)d_in[1];
    const float* props  = (const float*)d_in[2];
    const void*  hp     = (n_in > 3) ? d_in[3] : nullptr;
    const void*  wp     = (n_in > 4) ? d_in[4] : nullptr;
    float* out = (float*)d_out;

    k1_decode<<<(BB * NN + 255) / 256, 256>>>(logits, reg, props, hp, wp);
    k2_sort<<<BB, 512>>>();
    dim3 g3(64, 64, BB);
    k3_mask<<<g3, 64>>>();
    k4_scan<<<BB, 32>>>(out);
}